// round 17
// baseline (speedup 1.0000x reference)
#include <cuda_runtime.h>
#include <cuda_fp16.h>
#include <cstdint>

#define Bsz  64
#define Csz  256
#define HW   1024
#define CTR  528        // 16*32 + 16
#define KC   32         // K chunk (= 16 fp16x2 k-pairs)
#define NCH  8          // 256 / 32
#define SA2  264        // A smem k2-row stride (u32): 256 + 8
#define SB2  72         // B smem k2-row stride (u32): 64 + 8
#define BUFA (16 * SA2) // 4224 u32
#define BUFB (16 * SB2) // 1152 u32

// per-CTA partials: [z][ntile][o]
__device__ float g_S[2 * Bsz][16][Csz];
__device__ float g_P[2 * Bsz][16][Csz];

// per-z folded A operand packed as fp16x2 over k-pairs
__device__ uint32_t g_Wzh[2 * Bsz][Csz / 2][Csz];   // 16.8 MB (L2-resident)

__device__ __forceinline__ uint32_t packf16(float lo, float hi) {
    uint32_t d;
    asm("cvt.rn.f16x2.f32 %0, %1, %2;" : "=r"(d) : "f"(hi), "f"(lo));
    return d;
}

__device__ __forceinline__ void mma16(float* c, const uint32_t* a,
                                      uint32_t b0, uint32_t b1) {
    asm volatile(
        "mma.sync.aligned.m16n8k16.row.col.f32.f16.f16.f32 "
        "{%0,%1,%2,%3}, {%4,%5,%6,%7}, {%8,%9}, {%0,%1,%2,%3};"
        : "+f"(c[0]), "+f"(c[1]), "+f"(c[2]), "+f"(c[3])
        : "r"(a[0]), "r"(a[1]), "r"(a[2]), "r"(a[3]), "r"(b0), "r"(b1));
}

__device__ __forceinline__ uint32_t smem_u32(const void* p) {
    uint32_t a;
    asm("{ .reg .u64 t; cvta.to.shared.u64 t, %1; cvt.u32.u64 %0, t; }" : "=r"(a) : "l"(p));
    return a;
}

// ---------------------------------------------------------------------------
// fused prep, z-amortized: each block folds one 32-k tile for 4 z values.
// Wzh[z][k2][m] = fp16x2(W[m][2k2]   + W[m][256]*cen_z(2k2),
//                        W[m][2k2+1] + W[m][256]*cen_z(2k2+1))
// grid (8 k-tiles, 32 z-groups), block 512  -> 256 blocks, 2-3 resident/SM
// ---------------------------------------------------------------------------
__global__ void __launch_bounds__(512)
build_wzh(const float* __restrict__ x1, const float* __restrict__ x2,
          const float* __restrict__ w) {
    __shared__ float wt[32][257];     // [kk][m]; stride 257 -> conflict-free
    __shared__ float wc_s[256];
    __shared__ float cen_s[4][32];

    const int k0 = blockIdx.x * 32;
    const int zg = blockIdx.y * 4;
    const int tid = threadIdx.x;

    // W tile: per-warp one m-row, 32 consecutive k (coalesced 128 B)
#pragma unroll
    for (int q = 0; q < 16; ++q) {
        int e = tid + q * 512;
        int m = e >> 5, kk = e & 31;
        wt[kk][m] = w[(size_t)m * 257 + k0 + kk];
    }
    if (tid < 128) {
        // cen for 4 z values (scattered, once per block)
        int zi = tid >> 5, kk = tid & 31;
        int z = zg + zi;
        const float* xz = ((z >> 6) ? x2 : x1) + (size_t)(z & 63) * Csz * HW;
        cen_s[zi][kk] = xz[(size_t)(k0 + kk) * HW + CTR] * (1.0f / 256.0f);
    } else if (tid < 384) {
        int m = tid - 128;
        wc_s[m] = w[(size_t)m * 257 + 256];
    }
    __syncthreads();

    // two (k2l, m4) slices per thread; 4 z each
#pragma unroll
    for (int q = 0; q < 2; ++q) {
        const int idx = tid + q * 512;
        const int k2l = idx >> 6;                // 0..15
        const int m4 = (idx & 63) * 4;
        float wt0[4], wt1[4], wc4[4];
#pragma unroll
        for (int i = 0; i < 4; ++i) {
            wt0[i] = wt[2 * k2l][m4 + i];
            wt1[i] = wt[2 * k2l + 1][m4 + i];
            wc4[i] = wc_s[m4 + i];
        }
        const int k2 = (k0 >> 1) + k2l;
#pragma unroll
        for (int zi = 0; zi < 4; ++zi) {
            const int z = zg + zi;
            const float c0 = cen_s[zi][2 * k2l];     // warp-broadcast
            const float c1 = cen_s[zi][2 * k2l + 1];
            uint4 v;
            v.x = packf16(wt0[0] + wc4[0] * c0, wt1[0] + wc4[0] * c1);
            v.y = packf16(wt0[1] + wc4[1] * c0, wt1[1] + wc4[1] * c1);
            v.z = packf16(wt0[2] + wc4[2] * c0, wt1[2] + wc4[2] * c1);
            v.w = packf16(wt0[3] + wc4[3] * c0, wt1[3] + wc4[3] * c1);
            *(uint4*)&g_Wzh[z][k2][m4] = v;          // coalesced 16 B
        }
    }
}

// ---------------------------------------------------------------------------
// main GEMM (fp16 in, fp32 acc) + fused sigmoid-pool  (R11/R15/R16, verbatim)
// grid (16 n-tiles, 128 z), block 256 (8 warps = 8M x 1N; warp tile 32 x 64)
// ---------------------------------------------------------------------------
__global__ void __launch_bounds__(256, 2)
gemm_pool_kernel(const float* __restrict__ x1, const float* __restrict__ x2) {
    extern __shared__ uint32_t sm[];
    uint32_t* Ab[2] = { sm, sm + BUFA };
    uint32_t* Bb[2] = { sm + 2 * BUFA, sm + 2 * BUFA + BUFB };
    uint32_t* stash = sm + 2 * BUFA + 2 * BUFB;   // 128 k2-rows x SB2

    const int tid = threadIdx.x;
    const int z = blockIdx.y;
    const int branch = z >> 6, b = z & 63;
    const float* xz = (branch ? x2 : x1) + (size_t)b * Csz * HW;
    const int n0 = blockIdx.x * 64;
    const uint32_t* wzh = &g_Wzh[z][0][0];        // [128 k2][256 m]

    const uint32_t sA0 = smem_u32(Ab[0]);
    const uint32_t sA1 = smem_u32(Ab[1]);

    float4 Brf0, Brf1;

#define CPA(kc, sbase) { _Pragma("unroll") for (int q = 0; q < 4; ++q) {       \
        int idx = tid + q * 256;                                               \
        uint32_t dst = (sbase) + ((idx >> 6) * SA2 + (idx & 63) * 4) * 4;      \
        const uint32_t* src = wzh + (size_t)((kc) * 16 + (idx >> 6)) * 256     \
                              + (idx & 63) * 4;                                \
        asm volatile("cp.async.cg.shared.global [%0], [%1], 16;"               \
                     :: "r"(dst), "l"(src)); }                                 \
    asm volatile("cp.async.commit_group;"); }
#define LD_B(kc) {                                                             \
        const float* p0 = xz + (size_t)((kc) * KC + 2 * (tid >> 4)) * HW       \
                          + n0 + (tid & 15) * 4;                               \
        Brf0 = *(const float4*)p0;                                             \
        Brf1 = *(const float4*)(p0 + HW); }
#define ST_B(buf, kc) {                                                        \
        uint4 v;                                                               \
        v.x = packf16(Brf0.x, Brf1.x);                                         \
        v.y = packf16(Brf0.y, Brf1.y);                                         \
        v.z = packf16(Brf0.z, Brf1.z);                                         \
        v.w = packf16(Brf0.w, Brf1.w);                                         \
        *(uint4*)(Bb[buf] + (tid >> 4) * SB2 + (tid & 15) * 4) = v;            \
        *(uint4*)(stash + ((kc) * 16 + (tid >> 4)) * SB2 + (tid & 15) * 4) = v; }

    // ---- MMA mapping: 8 warps stacked in M; warp tile 32 x 64
    const int lane = tid & 31;
    const int wid = tid >> 5;
    const int wm = wid * 32;
    const int g = lane >> 2, tg = lane & 3;

    float acc[2][8][4];
#pragma unroll
    for (int i = 0; i < 2; ++i)
#pragma unroll
        for (int j = 0; j < 8; ++j)
#pragma unroll
            for (int r = 0; r < 4; ++r) acc[i][j][r] = 0.0f;

    CPA(0, sA0); LD_B(0); ST_B(0, 0);
    asm volatile("cp.async.wait_group 0;");
    __syncthreads();

#pragma unroll
    for (int kc = 0; kc < NCH; ++kc) {
        const int buf = kc & 1;
        if (kc < NCH - 1) { CPA(kc + 1, buf ? sA0 : sA1); LD_B(kc + 1); }

        const uint32_t* A = Ab[buf];
        const uint32_t* B = Bb[buf];
#pragma unroll
        for (int ks = 0; ks < 2; ++ks) {
            const int ko = ks * 8;                 // k2 offset (8 pairs = k16)
            uint32_t a[2][4];
#pragma unroll
            for (int i = 0; i < 2; ++i) {
                const int rb = wm + i * 16 + g;
                a[i][0] = A[(ko + tg) * SA2 + rb];
                a[i][1] = A[(ko + tg) * SA2 + rb + 8];
                a[i][2] = A[(ko + tg + 4) * SA2 + rb];
                a[i][3] = A[(ko + tg + 4) * SA2 + rb + 8];
            }
#pragma unroll
            for (int j = 0; j < 8; ++j) {
                const int cb = j * 8 + g;
                uint32_t b0 = B[(ko + tg) * SB2 + cb];
                uint32_t b1 = B[(ko + tg + 4) * SB2 + cb];
#pragma unroll
                for (int i = 0; i < 2; ++i) mma16(acc[i][j], a[i], b0, b1);
            }
        }
        if (kc < NCH - 1) {
            ST_B(buf ^ 1, kc + 1);
            asm volatile("cp.async.wait_group 0;");
        }
        __syncthreads();
    }

    // ---- fused epilogue: sigmoid + pooled partials; x from fp16 stash
#pragma unroll
    for (int i = 0; i < 2; ++i) {
#pragma unroll
        for (int rs = 0; rs < 2; ++rs) {
            const int lrow = wm + i * 16 + g + rs * 8;      // 0..255
            const int k2L = lrow >> 1, h = lrow & 1;
            const uint32_t* srow = stash + k2L * SB2 + 2 * tg;
            float sS = 0.0f, sP = 0.0f;
#pragma unroll
            for (int j = 0; j < 8; ++j) {
                uint2 u = *(const uint2*)(srow + j * 8);
                __half2 p0 = *reinterpret_cast<__half2*>(&u.x);
                __half2 p1 = *reinterpret_cast<__half2*>(&u.y);
                float xv0 = h ? __high2float(p0) : __low2float(p0);
                float xv1 = h ? __high2float(p1) : __low2float(p1);
                float v0 = acc[i][j][2 * rs];
                float v1 = acc[i][j][2 * rs + 1];
                float s0 = __fdividef(1.0f, 1.0f + __expf(-v0));
                float s1 = __fdividef(1.0f, 1.0f + __expf(-v1));
                sS += s0 + s1;
                sP += s0 * xv0 + s1 * xv1;
            }
            sS += __shfl_xor_sync(0xffffffffu, sS, 1);
            sS += __shfl_xor_sync(0xffffffffu, sS, 2);
            sP += __shfl_xor_sync(0xffffffffu, sP, 1);
            sP += __shfl_xor_sync(0xffffffffu, sP, 2);
            if (tg == 0) {
                g_S[z][blockIdx.x][lrow] = sS;
                g_P[z][blockIdx.x][lrow] = sP;
            }
        }
    }
}

// ---------------------------------------------------------------------------
// finalize (verbatim): 8 threads per output; per-branch divide, then
// cross-branch add. grid 512 x block 256 -> 32 outputs/block
// ---------------------------------------------------------------------------
__global__ void finalize_kernel(float* __restrict__ out) {
    const int tid = threadIdx.x;
    const int i = blockIdx.x * 32 + (tid >> 3);   // output index (b*256+o)
    const int part = tid & 7;                      // br = part>>2, quarter = part&3
    const int b = i >> 8, o = i & 255;
    const int br = part >> 2;
    const int z = br * Bsz + b;
    const int s0 = (part & 3) * 4;

    float S = (g_S[z][s0][o] + g_S[z][s0 + 1][o])
            + (g_S[z][s0 + 2][o] + g_S[z][s0 + 3][o]);
    float P = (g_P[z][s0][o] + g_P[z][s0 + 1][o])
            + (g_P[z][s0 + 2][o] + g_P[z][s0 + 3][o]);
    // reduce the 4 quarters within each branch (lanes differ in bits 0..1)
    S += __shfl_xor_sync(0xffffffffu, S, 1);
    P += __shfl_xor_sync(0xffffffffu, P, 1);
    S += __shfl_xor_sync(0xffffffffu, S, 2);
    P += __shfl_xor_sync(0xffffffffu, P, 2);
    float r = P / (S + 1e-8f);
    // add the two branches (lanes differ in bit 2)
    r += __shfl_xor_sync(0xffffffffu, r, 4);
    if (part == 0) out[i] = r;
}

// ---------------------------------------------------------------------------
extern "C" void kernel_launch(void* const* d_in, const int* in_sizes, int n_in,
                              void* d_out, int out_size) {
    const float* x1 = (const float*)d_in[0];
    const float* x2 = (const float*)d_in[1];
    const float* w  = (const float*)d_in[2];
    // d_in[3..6] (ca_*) are mathematically unused: softmax over a size-1 axis == 1.
    float* out = (float*)d_out;

    constexpr int SMEM_SZ = (2 * BUFA + 2 * BUFB + 128 * SB2) * 4;   // 79872 B
    cudaFuncSetAttribute(gemm_pool_kernel,
                         cudaFuncAttributeMaxDynamicSharedMemorySize, SMEM_SZ);

    build_wzh<<<dim3(8, 32), 512>>>(x1, x2, w);
    gemm_pool_kernel<<<dim3(16, 2 * Bsz), 256, SMEM_SZ>>>(x1, x2);
    finalize_kernel<<<512, 256>>>(out);
}